// round 10
// baseline (speedup 1.0000x reference)
#include <cuda_runtime.h>
#include <cuda_bf16.h>
#include <cub/cub.cuh>
#include <math.h>

#define NNODES 10000
#define BATCH  2000
#define NPAIRS (BATCH*(BATCH-1)/2)   /* 1999000 */
#define EMAX   5000000
#define SEL_THREADS 1024
#define RCAP 768                     /* per-row capacity: mean 500, +12 sigma */

// ---------------- static device scratch (no allocations allowed) -----------
__device__ unsigned int g_kin [EMAX];
__device__ unsigned int g_kout[EMAX];
__device__ unsigned int g_vin [EMAX];
__device__ unsigned int g_vout[EMAX];
__device__ unsigned int g_rcnt[NNODES];
__device__ unsigned int g_roff[NNODES + 1];
__device__ unsigned int g_scores[NNODES];
__device__ unsigned int g_nodes[BATCH];
__device__ int          g_flags[NNODES];
__device__ unsigned char g_temp[64u * 1024u * 1024u];

__device__ __forceinline__ unsigned int rotl32(unsigned int x, unsigned int d) {
    return (x << d) | (x >> (32u - d));
}

// ---------------- node chain: scores / select / pairs ----------------------
__global__ void k_scores() {
    int w = blockIdx.x * blockDim.x + threadIdx.x;
    if (w >= NNODES) return;
    const unsigned int k0 = 0u, k1 = 19u;
    const unsigned int ks[3] = { k0, k1, k0 ^ k1 ^ 0x1BD11BDAu };
    const unsigned int rotA[4] = {13u, 15u, 26u, 6u};
    const unsigned int rotB[4] = {17u, 29u, 16u, 24u};
    unsigned int x0 = 0u, x1 = (unsigned int)w;
    x0 += ks[0]; x1 += ks[1];
    #pragma unroll
    for (int i = 0; i < 5; i++) {
        #pragma unroll
        for (int r = 0; r < 4; r++) {
            unsigned int rot = (i & 1) ? rotB[r] : rotA[r];
            x0 += x1; x1 = rotl32(x1, rot); x1 ^= x0;
        }
        x0 += ks[(i + 1) % 3];
        x1 += ks[(i + 2) % 3] + (unsigned int)(i + 1);
    }
    unsigned int bits = x0 ^ x1;
    float f = __uint_as_float((bits >> 9) | 0x3F800000u) - 1.0f;
    float u = fmaxf(f, 1.17549435e-38f);
    float g = -logf(-logf(u));
    float s = (w > 0) ? (logf((float)w) + g) : -INFINITY;
    unsigned int b = __float_as_uint(s);
    unsigned int m = (b & 0x80000000u) ? ~b : (b | 0x80000000u);
    g_scores[w] = m;
}

__global__ void __launch_bounds__(SEL_THREADS) k_select(float* __restrict__ out) {
    __shared__ unsigned int s[NNODES];
    __shared__ unsigned int hist[256];
    __shared__ unsigned int sh_b, sh_rem, sh_run_eq, sh_run_sel;
    typedef cub::BlockScan<unsigned int, SEL_THREADS> Scan;
    __shared__ typename Scan::TempStorage scan_tmp;

    int tid = threadIdx.x;
    for (int e = tid; e < NNODES; e += SEL_THREADS) s[e] = g_scores[e];
    if (tid == 0) { sh_rem = BATCH; sh_run_eq = 0; sh_run_sel = 0; }
    __syncthreads();

    unsigned int prefix = 0;
    #pragma unroll
    for (int shift = 24; shift >= 0; shift -= 8) {
        if (tid < 256) hist[tid] = 0;
        __syncthreads();
        unsigned int mask_hi = (shift == 24) ? 0u : (0xFFFFFFFFu << (shift + 8));
        for (int e = tid; e < NNODES; e += SEL_THREADS) {
            unsigned int v = s[e];
            if (((v ^ prefix) & mask_hi) == 0u)
                atomicAdd(&hist[(v >> shift) & 255u], 1u);
        }
        __syncthreads();
        if (tid == 0) {
            unsigned int rem = sh_rem, acc = 0; int b = 0;
            for (int k = 255; k >= 0; k--) {
                unsigned int c = hist[k];
                if (acc + c >= rem) { b = k; break; }
                acc += c;
            }
            sh_b = (unsigned int)b; sh_rem = rem - acc;
        }
        __syncthreads();
        prefix |= sh_b << shift;
        __syncthreads();
    }
    unsigned int thr = prefix, rem = sh_rem;

    for (int base = 0; base < NNODES; base += SEL_THREADS) {
        int e = base + tid;
        unsigned int v = (e < NNODES) ? s[e] : 0u;
        unsigned int is_eq = (e < NNODES && v == thr) ? 1u : 0u;
        unsigned int is_gt = (e < NNODES && v >  thr) ? 1u : 0u;
        unsigned int eq_rank, eq_tot;
        Scan(scan_tmp).ExclusiveSum(is_eq, eq_rank, eq_tot);
        __syncthreads();
        unsigned int sel = is_gt | ((is_eq && (sh_run_eq + eq_rank) < rem) ? 1u : 0u);
        unsigned int pos, sel_tot;
        Scan(scan_tmp).ExclusiveSum(sel, pos, sel_tot);
        __syncthreads();
        unsigned int gpos = sh_run_sel + pos;
        if (e < NNODES) {
            g_flags[e] = (int)sel;
            if (sel) { g_nodes[gpos] = (unsigned int)e; out[gpos] = (float)e; }
        }
        __syncthreads();
        if (tid == 0) { sh_run_eq += eq_tot; sh_run_sel += sel_tot; }
        __syncthreads();
    }
}

__global__ void k_pairs(float* __restrict__ out) {
    int p = blockIdx.x * blockDim.x + threadIdx.x;
    if (p >= NPAIRS) return;
    const float A = 2.0f * BATCH - 1.0f;
    float disc = A * A - 8.0f * (float)p;
    int i = (int)((A - sqrtf(fmaxf(disc, 0.0f))) * 0.5f);
    if (i < 0) i = 0;
    if (i > BATCH - 2) i = BATCH - 2;
    while (i > 0 && (long long)i * (2 * BATCH - i - 1) / 2 > (long long)p) i--;
    while ((long long)(i + 1) * (2 * BATCH - i - 2) / 2 <= (long long)p) i++;
    long long bse = (long long)i * (2 * BATCH - i - 1) / 2;
    int j = i + 1 + (int)((long long)p - bse);
    out[BATCH + p]          = (float)__ldg(&g_nodes[i]);
    out[BATCH + NPAIRS + p] = (float)__ldg(&g_nodes[j]);
}

// ---------------- zero row counters -----------------------------------------
__global__ void k_zero() {
    int t = blockIdx.x * blockDim.x + threadIdx.x;
    if (t < NNODES) g_rcnt[t] = 0;
}

// ---------------- keygen: key = i<<18 | j<<4 | state, val = time; row hist --
__global__ void k_keygen(const int* __restrict__ edges,
                         const float* __restrict__ times,
                         const int* __restrict__ states, int E) {
    int t4 = (blockIdx.x * blockDim.x + threadIdx.x) * 4;
    if (t4 >= E) return;
    if (t4 + 3 < E) {
        int4 iv = *(const int4*)(edges + t4);
        int4 jv = *(const int4*)(edges + E + t4);
        int4 sv = *(const int4*)(states + t4);
        uint4 tv = *(const uint4*)((const unsigned int*)times + t4);
        uint4 kv;
        kv.x = ((unsigned int)iv.x << 18) | ((unsigned int)jv.x << 4) | ((unsigned int)sv.x & 1u);
        kv.y = ((unsigned int)iv.y << 18) | ((unsigned int)jv.y << 4) | ((unsigned int)sv.y & 1u);
        kv.z = ((unsigned int)iv.z << 18) | ((unsigned int)jv.z << 4) | ((unsigned int)sv.z & 1u);
        kv.w = ((unsigned int)iv.w << 18) | ((unsigned int)jv.w << 4) | ((unsigned int)sv.w & 1u);
        *(uint4*)(g_kin + t4) = kv;
        *(uint4*)(g_vin + t4) = tv;
        atomicAdd(&g_rcnt[iv.x], 1u);
        atomicAdd(&g_rcnt[iv.y], 1u);
        atomicAdd(&g_rcnt[iv.z], 1u);
        atomicAdd(&g_rcnt[iv.w], 1u);
    } else {
        for (int t = t4; t < E; t++) {
            int i = edges[t], j = edges[E + t];
            g_kin[t] = ((unsigned int)i << 18) | ((unsigned int)j << 4) |
                       ((unsigned int)states[t] & 1u);
            g_vin[t] = __float_as_uint(times[t]);
            atomicAdd(&g_rcnt[i], 1u);
        }
    }
}

// ---------------- exclusive scan of row counts -> row offsets ---------------
__global__ void __launch_bounds__(1024) k_scanrows() {
    typedef cub::BlockScan<unsigned int, 1024> Scan;
    __shared__ typename Scan::TempStorage tmp;
    int t = threadIdx.x;
    unsigned int v[10], agg = 0;
    #pragma unroll
    for (int k = 0; k < 10; k++) {
        int idx = t * 10 + k;
        v[k] = (idx < NNODES) ? g_rcnt[idx] : 0u;
        agg += v[k];
    }
    unsigned int pre, total;
    Scan(tmp).ExclusiveSum(agg, pre, total);
    unsigned int run = pre;
    #pragma unroll
    for (int k = 0; k < 10; k++) {
        int idx = t * 10 + k;
        if (idx < NNODES) g_roff[idx] = run;
        run += v[k];
    }
    if (t == 0) g_roff[NNODES] = total;
}

// ---------------- per-row counting sort by j + fused epilogue ---------------
// One block per row r. Edges of row r are contiguous (stable i-sort) at
// [roff, roff+cnt) in original order. Counting sort over j with exact
// original-order stability via warp-0 match_any placement.
__global__ void __launch_bounds__(256) k_rowsort(const unsigned int* __restrict__ skeys,
                                                 const unsigned int* __restrict__ svals,
                                                 float* __restrict__ out, int E) {
    __shared__ unsigned int cnt[NNODES];       // 40 KB j-bins
    __shared__ unsigned int skey[RCAP];        // 3 KB
    __shared__ unsigned short spos[RCAP];      // 1.5 KB
    typedef cub::BlockScan<unsigned int, 256> Scan;
    __shared__ typename Scan::TempStorage stmp;

    int r = blockIdx.x;
    unsigned int off = g_roff[r];
    unsigned int n = g_roff[r + 1] - off;
    if (n == 0) return;
    if (n > RCAP) n = RCAP;   // statistically impossible; memory safety only
    int tid = threadIdx.x;
    int flag_r = g_flags[r];

    // zero bins + load row keys
    for (int idx = tid; idx < NNODES; idx += 256) cnt[idx] = 0;
    for (unsigned int e = tid; e < n; e += 256) skey[e] = skeys[off + e];
    __syncthreads();

    // histogram j
    for (unsigned int e = tid; e < n; e += 256)
        atomicAdd(&cnt[(skey[e] >> 4) & 0x3FFFu], 1u);
    __syncthreads();

    // two-level exclusive scan of 10000 bins (40 bins/thread)
    {
        int base_i = tid * 40;
        unsigned int tsum = 0;
        for (int k = 0; k < 40; k++) {
            int idx = base_i + k;
            if (idx < NNODES) tsum += cnt[idx];
        }
        unsigned int tbase;
        Scan(stmp).ExclusiveSum(tsum, tbase);
        unsigned int run = tbase;
        for (int k = 0; k < 40; k++) {
            int idx = base_i + k;
            if (idx < NNODES) { unsigned int c = cnt[idx]; cnt[idx] = run; run += c; }
        }
    }
    __syncthreads();

    // stable placement: warp 0 walks edges in original order, 32 at a time
    if (tid < 32) {
        int lane = tid;
        for (unsigned int b = 0; b < n; b += 32) {
            unsigned int e = b + lane;
            bool act = e < n;
            unsigned int j = act ? ((skey[e] >> 4) & 0x3FFFu) : (16384u + lane);
            unsigned int mask = __match_any_sync(0xFFFFFFFFu, j);
            unsigned int rank = __popc(mask & ((1u << lane) - 1u));
            int leader = __ffs(mask) - 1;
            unsigned int old = 0;
            if (lane == leader && act) old = atomicAdd(&cnt[j], __popc(mask));
            old = __shfl_sync(0xFFFFFFFFu, old, leader);
            if (act) spos[e] = (unsigned short)(old + rank);
        }
    }
    __syncthreads();

    // fused epilogue: all threads write the five output streams
    const long long OFF_E = (long long)BATCH + 2LL * NPAIRS;
    const long long OFF_T = OFF_E + 2LL * E;
    const long long OFF_S = OFF_T + E;
    const long long OFF_M = OFF_S + E;

    for (unsigned int e = tid; e < n; e += 256) {
        unsigned int gk = skey[e];
        int j  = (int)((gk >> 4) & 0x3FFFu);
        int st = (int)(gk & 1u);
        float tm = __uint_as_float(__ldg(&svals[off + e]));
        int m = flag_r & g_flags[j];
        unsigned int p = off + (unsigned int)spos[e];
        out[OFF_E + p]     = (float)r;
        out[OFF_E + E + p] = (float)j;
        out[OFF_T + p]     = m ? tm : 0.0f;
        out[OFF_S + p]     = m ? (float)st : 0.0f;
        out[OFF_M + p]     = (float)m;
    }
}

// ---------------- launcher ---------------------------------------------------
extern "C" void kernel_launch(void* const* d_in, const int* in_sizes, int n_in,
                              void* d_out, int out_size) {
    const int*   edges  = (const int*)d_in[0];
    const float* times  = (const float*)d_in[1];
    const int*   states = (const int*)d_in[2];
    int E = in_sizes[1];
    if (E > EMAX) E = EMAX;
    float* out = (float*)d_out;

    static cudaStream_t s_side = nullptr;
    static cudaEvent_t ev_fork = nullptr, ev_join = nullptr;
    if (s_side == nullptr) {
        cudaStreamCreateWithFlags(&s_side, cudaStreamNonBlocking);
        cudaEventCreateWithFlags(&ev_fork, cudaEventDisableTiming);
        cudaEventCreateWithFlags(&ev_join, cudaEventDisableTiming);
    }

    void *kin, *kout, *vin, *vout, *temp;
    cudaGetSymbolAddress(&kin,  g_kin);
    cudaGetSymbolAddress(&kout, g_kout);
    cudaGetSymbolAddress(&vin,  g_vin);
    cudaGetSymbolAddress(&vout, g_vout);
    cudaGetSymbolAddress(&temp, g_temp);
    const size_t temp_cap = 64u * 1024u * 1024u;

    // ---- fork: node chain on the proven single side stream ------------------
    cudaEventRecord(ev_fork, 0);
    cudaStreamWaitEvent(s_side, ev_fork, 0);
    k_scores<<<(NNODES + 255) / 256, 256, 0, s_side>>>();
    k_select<<<1, SEL_THREADS, 0, s_side>>>(out);
    k_pairs<<<(NPAIRS + 255) / 256, 256, 0, s_side>>>(out);
    cudaEventRecord(ev_join, s_side);

    // ---- main: row histogram + keygen, then 2-pass stable sort on i ---------
    k_zero<<<(NNODES + 255) / 256, 256>>>();
    k_keygen<<<(E / 4 + 255) / 256, 256>>>(edges, times, states, E);

    cub::DoubleBuffer<unsigned int> dk((unsigned int*)kin, (unsigned int*)kout);
    cub::DoubleBuffer<unsigned int> dv((unsigned int*)vin, (unsigned int*)vout);
    size_t tb = 0;
    cub::DeviceRadixSort::SortPairs(nullptr, tb, dk, dv, E, 18, 32);
    if (tb > temp_cap) tb = temp_cap;
    cub::DeviceRadixSort::SortPairs(temp, tb, dk, dv, E, 18, 32);

    k_scanrows<<<1, 1024>>>();

    // ---- join node chain (flags), then per-row counting sort + epilogue -----
    cudaStreamWaitEvent(0, ev_join, 0);
    k_rowsort<<<NNODES, 256>>>(dk.Current(), dv.Current(), out, E);
}

// round 12
// speedup vs baseline: 1.3276x; 1.3276x over previous
#include <cuda_runtime.h>
#include <cuda_bf16.h>
#include <cub/cub.cuh>
#include <math.h>

#define NNODES 10000
#define BATCH  2000
#define NPAIRS (BATCH*(BATCH-1)/2)   /* 1999000 */
#define EMAX   5000000
#define SEL_THREADS 1024

#define PB     1024                  /* hist/finish blocks */
#define NBINS  768                   /* flat>>16 < 763 */

// ---------------- static device scratch (no allocations allowed) -----------
__device__ unsigned int g_kin [EMAX];
__device__ unsigned int g_kout[EMAX];
__device__ unsigned int g_vin [EMAX];
__device__ unsigned int g_vout[EMAX];
__device__ unsigned int g_hp  [NBINS * PB];   // per-(bin,block) counts -> prefixes
__device__ unsigned int g_btot[NBINS];
__device__ unsigned int g_bbase[NBINS];
__device__ unsigned int g_scores[NNODES];
__device__ unsigned int g_nodes[BATCH];
__device__ int          g_flags[NNODES];
__device__ unsigned char g_temp[96u * 1024u * 1024u];

__device__ __forceinline__ unsigned int rotl32(unsigned int x, unsigned int d) {
    return (x << d) | (x >> (32u - d));
}

// ---------------- node chain: scores / select / pairs ----------------------
__global__ void k_scores() {
    int w = blockIdx.x * blockDim.x + threadIdx.x;
    if (w >= NNODES) return;
    const unsigned int k0 = 0u, k1 = 19u;
    const unsigned int ks[3] = { k0, k1, k0 ^ k1 ^ 0x1BD11BDAu };
    const unsigned int rotA[4] = {13u, 15u, 26u, 6u};
    const unsigned int rotB[4] = {17u, 29u, 16u, 24u};
    unsigned int x0 = 0u, x1 = (unsigned int)w;
    x0 += ks[0]; x1 += ks[1];
    #pragma unroll
    for (int i = 0; i < 5; i++) {
        #pragma unroll
        for (int r = 0; r < 4; r++) {
            unsigned int rot = (i & 1) ? rotB[r] : rotA[r];
            x0 += x1; x1 = rotl32(x1, rot); x1 ^= x0;
        }
        x0 += ks[(i + 1) % 3];
        x1 += ks[(i + 2) % 3] + (unsigned int)(i + 1);
    }
    unsigned int bits = x0 ^ x1;
    float f = __uint_as_float((bits >> 9) | 0x3F800000u) - 1.0f;
    float u = fmaxf(f, 1.17549435e-38f);
    float g = -logf(-logf(u));
    float s = (w > 0) ? (logf((float)w) + g) : -INFINITY;
    unsigned int b = __float_as_uint(s);
    unsigned int m = (b & 0x80000000u) ? ~b : (b | 0x80000000u);
    g_scores[w] = m;
}

__global__ void __launch_bounds__(SEL_THREADS) k_select(float* __restrict__ out) {
    __shared__ unsigned int s[NNODES];
    __shared__ unsigned int hist[256];
    __shared__ unsigned int sh_b, sh_rem, sh_run_eq, sh_run_sel;
    typedef cub::BlockScan<unsigned int, SEL_THREADS> Scan;
    __shared__ typename Scan::TempStorage scan_tmp;

    int tid = threadIdx.x;
    for (int e = tid; e < NNODES; e += SEL_THREADS) s[e] = g_scores[e];
    if (tid == 0) { sh_rem = BATCH; sh_run_eq = 0; sh_run_sel = 0; }
    __syncthreads();

    unsigned int prefix = 0;
    #pragma unroll
    for (int shift = 24; shift >= 0; shift -= 8) {
        if (tid < 256) hist[tid] = 0;
        __syncthreads();
        unsigned int mask_hi = (shift == 24) ? 0u : (0xFFFFFFFFu << (shift + 8));
        for (int e = tid; e < NNODES; e += SEL_THREADS) {
            unsigned int v = s[e];
            if (((v ^ prefix) & mask_hi) == 0u)
                atomicAdd(&hist[(v >> shift) & 255u], 1u);
        }
        __syncthreads();
        if (tid == 0) {
            unsigned int rem = sh_rem, acc = 0; int b = 0;
            for (int k = 255; k >= 0; k--) {
                unsigned int c = hist[k];
                if (acc + c >= rem) { b = k; break; }
                acc += c;
            }
            sh_b = (unsigned int)b; sh_rem = rem - acc;
        }
        __syncthreads();
        prefix |= sh_b << shift;
        __syncthreads();
    }
    unsigned int thr = prefix, rem = sh_rem;

    for (int base = 0; base < NNODES; base += SEL_THREADS) {
        int e = base + tid;
        unsigned int v = (e < NNODES) ? s[e] : 0u;
        unsigned int is_eq = (e < NNODES && v == thr) ? 1u : 0u;
        unsigned int is_gt = (e < NNODES && v >  thr) ? 1u : 0u;
        unsigned int eq_rank, eq_tot;
        Scan(scan_tmp).ExclusiveSum(is_eq, eq_rank, eq_tot);
        __syncthreads();
        unsigned int sel = is_gt | ((is_eq && (sh_run_eq + eq_rank) < rem) ? 1u : 0u);
        unsigned int pos, sel_tot;
        Scan(scan_tmp).ExclusiveSum(sel, pos, sel_tot);
        __syncthreads();
        unsigned int gpos = sh_run_sel + pos;
        if (e < NNODES) {
            g_flags[e] = (int)sel;
            if (sel) { g_nodes[gpos] = (unsigned int)e; out[gpos] = (float)e; }
        }
        __syncthreads();
        if (tid == 0) { sh_run_eq += eq_tot; sh_run_sel += sel_tot; }
        __syncthreads();
    }
}

__global__ void k_pairs(float* __restrict__ out) {
    int p = blockIdx.x * blockDim.x + threadIdx.x;
    if (p >= NPAIRS) return;
    const float A = 2.0f * BATCH - 1.0f;
    float disc = A * A - 8.0f * (float)p;
    int i = (int)((A - sqrtf(fmaxf(disc, 0.0f))) * 0.5f);
    if (i < 0) i = 0;
    if (i > BATCH - 2) i = BATCH - 2;
    while (i > 0 && (long long)i * (2 * BATCH - i - 1) / 2 > (long long)p) i--;
    while ((long long)(i + 1) * (2 * BATCH - i - 2) / 2 <= (long long)p) i++;
    long long bse = (long long)i * (2 * BATCH - i - 1) / 2;
    int j = i + 1 + (int)((long long)p - bse);
    out[BATCH + p]          = (float)__ldg(&g_nodes[i]);
    out[BATCH + NPAIRS + p] = (float)__ldg(&g_nodes[j]);
}

// ---------------- keygen: key = flat<<6 | state, val = time -----------------
__global__ void k_ekeys4(const int* __restrict__ edges,
                         const float* __restrict__ times,
                         const int* __restrict__ states, int E) {
    int t4 = (blockIdx.x * blockDim.x + threadIdx.x) * 4;
    if (t4 >= E) return;
    if (t4 + 3 < E) {
        int4 iv = *(const int4*)(edges + t4);
        int4 jv = *(const int4*)(edges + E + t4);
        int4 sv = *(const int4*)(states + t4);
        uint4 tv = *(const uint4*)((const unsigned int*)times + t4);
        uint4 kv;
        kv.x = ((unsigned int)(iv.x * NNODES - (iv.x * (iv.x + 1)) / 2 + (jv.x - iv.x - 1)) << 6) | ((unsigned int)sv.x & 1u);
        kv.y = ((unsigned int)(iv.y * NNODES - (iv.y * (iv.y + 1)) / 2 + (jv.y - iv.y - 1)) << 6) | ((unsigned int)sv.y & 1u);
        kv.z = ((unsigned int)(iv.z * NNODES - (iv.z * (iv.z + 1)) / 2 + (jv.z - iv.z - 1)) << 6) | ((unsigned int)sv.z & 1u);
        kv.w = ((unsigned int)(iv.w * NNODES - (iv.w * (iv.w + 1)) / 2 + (jv.w - iv.w - 1)) << 6) | ((unsigned int)sv.w & 1u);
        *(uint4*)(g_kin + t4) = kv;
        *(uint4*)(g_vin + t4) = tv;
    } else {
        for (int t = t4; t < E; t++) {
            int i = edges[t], j = edges[E + t];
            unsigned int flat = (unsigned int)(i * NNODES - (i * (i + 1)) / 2 + (j - i - 1));
            g_kin[t] = (flat << 6) | ((unsigned int)states[t] & 1u);
            g_vin[t] = __float_as_uint(times[t]);
        }
    }
}

// ---------------- hist: per-(block,bin) counts over sorted keys -------------
__global__ void __launch_bounds__(256) k_hist(const unsigned int* __restrict__ keys,
                                              int E, int chunk) {
    __shared__ unsigned int h[NBINS];
    int blk = blockIdx.x;
    int start = blk * chunk, end = min(E, start + chunk);
    for (int b = threadIdx.x; b < NBINS; b += 256) h[b] = 0;
    __syncthreads();
    for (int t = start + threadIdx.x; t < end; t += 256)
        atomicAdd(&h[keys[t] >> 22], 1u);
    __syncthreads();
    for (int b = threadIdx.x; b < NBINS; b += 256)
        g_hp[b * PB + blk] = h[b];
}

// ---------------- S1: per-bin exclusive scan across blocks (warp per bin) ---
__global__ void __launch_bounds__(256) k_scan1() {
    int bin = blockIdx.x * 8 + (threadIdx.x >> 5);
    int lane = threadIdx.x & 31;
    if (bin >= NBINS) return;
    unsigned int run = 0;
    for (int c = 0; c < PB; c += 32) {
        unsigned int v = g_hp[bin * PB + c + lane];
        unsigned int x = v;
        #pragma unroll
        for (int d = 1; d < 32; d <<= 1) {
            unsigned int y = __shfl_up_sync(0xFFFFFFFFu, x, d);
            if (lane >= d) x += y;
        }
        g_hp[bin * PB + c + lane] = run + (x - v);
        run += __shfl_sync(0xFFFFFFFFu, x, 31);
    }
    if (lane == 0) g_btot[bin] = run;
}

// ---------------- S2: exclusive scan of bin totals ---------------------------
__global__ void __launch_bounds__(1024) k_scan2() {
    typedef cub::BlockScan<unsigned int, 1024> Scan;
    __shared__ typename Scan::TempStorage tmp;
    int t = threadIdx.x;
    unsigned int v = (t < NBINS) ? g_btot[t] : 0u;
    unsigned int pre;
    Scan(tmp).ExclusiveSum(v, pre);
    if (t < NBINS) g_bbase[t] = pre;
}

// ---------------- flat -> (i,j) decode ---------------------------------------
__device__ __forceinline__ long long rowbase(int i) {
    return (long long)i * (2 * NNODES - 1 - i) / 2;
}
__device__ __forceinline__ void decode_flat(unsigned int flat, int& i, int& j) {
    const float A = 2.0f * NNODES - 1.0f;
    float disc = A * A - 8.0f * (float)flat;
    i = (int)((A - sqrtf(fmaxf(disc, 0.0f))) * 0.5f);
    if (i < 0) i = 0;
    if (i > NNODES - 2) i = NNODES - 2;
    while (i > 0 && rowbase(i) > (long long)flat) i--;
    while (rowbase(i + 1) <= (long long)flat) i++;
    j = (int)((long long)flat - rowbase(i)) + i + 1;
}

// ---------------- finish: stable 768-bin partition fused with epilogue ------
// Warp-owned contiguous sub-chunks + warp-private counters: deterministic,
// original-order stable, ~3 block barriers total.
__global__ void __launch_bounds__(256) k_finish(const unsigned int* __restrict__ keys,
                                                const unsigned int* __restrict__ vals,
                                                float* __restrict__ out, int E, int chunk) {
    __shared__ unsigned int wcnt[8 * NBINS];   // 24 KB
    __shared__ unsigned int hpb[NBINS];
    int blk = blockIdx.x;
    int start = blk * chunk, end = min(E, start + chunk);
    int n = end - start;
    if (n <= 0) return;
    int tid = threadIdx.x, w = tid >> 5, lane = tid & 31;

    for (int x = tid; x < 8 * NBINS; x += 256) wcnt[x] = 0;
    __syncthreads();

    // warp sub-chunks (contiguous, in order)
    int per = (n + 7) / 8;
    int s0 = start + w * per;
    int s1 = min(end, s0 + per);

    // sweep A: per-warp per-bin counts (order-free)
    for (int t = s0 + lane; t < s1; t += 32)
        atomicAdd(&wcnt[w * NBINS + (keys[t] >> 22)], 1u);
    __syncthreads();

    // per-bin exclusive prefix over warps; load global bases
    for (int b = tid; b < NBINS; b += 256) {
        unsigned int acc = 0;
        #pragma unroll
        for (int ww = 0; ww < 8; ww++) {
            unsigned int c = wcnt[ww * NBINS + b];
            wcnt[ww * NBINS + b] = acc;
            acc += c;
        }
        hpb[b] = g_bbase[b] + g_hp[b * PB + blk];
    }
    __syncthreads();

    const long long OFF_E = (long long)BATCH + 2LL * NPAIRS;
    const long long OFF_T = OFF_E + 2LL * E;
    const long long OFF_S = OFF_T + E;
    const long long OFF_M = OFF_S + E;

    // sweep B: ordered, deterministic scatter + epilogue
    for (int t0 = s0; t0 < s1; t0 += 32) {
        int t = t0 + lane;
        bool act = t < s1;
        unsigned int key = act ? keys[t] : 0u;
        unsigned int bin = act ? (key >> 22) : (unsigned int)(NBINS + lane);
        unsigned int mask = __match_any_sync(0xFFFFFFFFu, bin);
        unsigned int rank = __popc(mask & ((1u << lane) - 1u));
        int leader = __ffs(mask) - 1;
        unsigned int base = 0;
        if (lane == leader && act) base = atomicAdd(&wcnt[w * NBINS + bin], __popc(mask));
        base = __shfl_sync(0xFFFFFFFFu, base, leader);
        if (act) {
            unsigned int pos = hpb[bin] + base + rank;
            unsigned int flat = key >> 6;
            int st = (int)(key & 1u);
            int i, j; decode_flat(flat, i, j);
            int m = g_flags[i] & g_flags[j];
            float tm = __uint_as_float(vals[t]);
            out[OFF_E + pos]     = (float)i;
            out[OFF_E + E + pos] = (float)j;
            out[OFF_T + pos]     = m ? tm : 0.0f;
            out[OFF_S + pos]     = m ? (float)st : 0.0f;
            out[OFF_M + pos]     = (float)m;
        }
    }
}

// ---------------- launcher ---------------------------------------------------
extern "C" void kernel_launch(void* const* d_in, const int* in_sizes, int n_in,
                              void* d_out, int out_size) {
    const int*   edges  = (const int*)d_in[0];
    const float* times  = (const float*)d_in[1];
    const int*   states = (const int*)d_in[2];
    int E = in_sizes[1];
    if (E > EMAX) E = EMAX;
    float* out = (float*)d_out;

    static cudaStream_t s_side = nullptr;
    static cudaEvent_t ev_fork = nullptr, ev_join = nullptr;
    if (s_side == nullptr) {
        cudaStreamCreateWithFlags(&s_side, cudaStreamNonBlocking);
        cudaEventCreateWithFlags(&ev_fork, cudaEventDisableTiming);
        cudaEventCreateWithFlags(&ev_join, cudaEventDisableTiming);
    }

    void *kin, *kout, *vin, *vout, *temp;
    cudaGetSymbolAddress(&kin,  g_kin);
    cudaGetSymbolAddress(&kout, g_kout);
    cudaGetSymbolAddress(&vin,  g_vin);
    cudaGetSymbolAddress(&vout, g_vout);
    cudaGetSymbolAddress(&temp, g_temp);
    const size_t temp_cap = 96u * 1024u * 1024u;

    // ---- fork: node chain on the proven single side stream ------------------
    cudaEventRecord(ev_fork, 0);
    cudaStreamWaitEvent(s_side, ev_fork, 0);
    k_scores<<<(NNODES + 255) / 256, 256, 0, s_side>>>();
    k_select<<<1, SEL_THREADS, 0, s_side>>>(out);
    k_pairs<<<(NPAIRS + 255) / 256, 256, 0, s_side>>>(out);
    cudaEventRecord(ev_join, s_side);

    // ---- main: keygen, 2-pass stable radix sort on bits [6,22) --------------
    k_ekeys4<<<(E / 4 + 255) / 256, 256>>>(edges, times, states, E);

    size_t tb = 0;
    cub::DeviceRadixSort::SortPairs(
        nullptr, tb, (const unsigned int*)kin, (unsigned int*)kout,
        (const unsigned int*)vin, (unsigned int*)vout, E, 6, 22);
    if (tb > temp_cap) tb = temp_cap;
    cub::DeviceRadixSort::SortPairs(
        temp, tb, (const unsigned int*)kin, (unsigned int*)kout,
        (const unsigned int*)vin, (unsigned int*)vout, E, 6, 22);

    // ---- 768-bin partition prep ---------------------------------------------
    int chunk = (E + PB - 1) / PB;
    k_hist<<<PB, 256>>>((const unsigned int*)kout, E, chunk);
    k_scan1<<<(NBINS + 7) / 8, 256>>>();
    k_scan2<<<1, 1024>>>();

    // ---- join node chain (flags), then fused partition+epilogue -------------
    cudaStreamWaitEvent(0, ev_join, 0);
    k_finish<<<PB, 256>>>((const unsigned int*)kout, (const unsigned int*)vout,
                          out, E, chunk);
}

// round 14
// speedup vs baseline: 1.9618x; 1.4777x over previous
#include <cuda_runtime.h>
#include <cuda_bf16.h>
#include <cub/cub.cuh>
#include <math.h>

#define NNODES 10000
#define BATCH  2000
#define NPAIRS (BATCH*(BATCH-1)/2)   /* 1999000 */
#define EMAX   5000000
#define SEL_THREADS 1024
#define PB 1024                      /* hist/finish partition blocks */

// ---------------- static device scratch (no allocations allowed) -----------
__device__ unsigned int g_kin [EMAX];
__device__ unsigned int g_kout[EMAX];
__device__ unsigned int g_vin [EMAX];
__device__ unsigned int g_vout[EMAX];
__device__ unsigned int g_hist4[PB * 4];
__device__ unsigned int g_base4[4];
__device__ unsigned int g_scores[NNODES];
__device__ unsigned int g_nodes[BATCH];
__device__ int          g_flags[NNODES];
__device__ unsigned char g_temp[96u * 1024u * 1024u];

__device__ __forceinline__ unsigned int rotl32(unsigned int x, unsigned int d) {
    return (x << d) | (x >> (32u - d));
}

// ---------------- node chain: scores / select / pairs ----------------------
__global__ void k_scores() {
    int w = blockIdx.x * blockDim.x + threadIdx.x;
    if (w >= NNODES) return;
    const unsigned int k0 = 0u, k1 = 19u;
    const unsigned int ks[3] = { k0, k1, k0 ^ k1 ^ 0x1BD11BDAu };
    const unsigned int rotA[4] = {13u, 15u, 26u, 6u};
    const unsigned int rotB[4] = {17u, 29u, 16u, 24u};
    unsigned int x0 = 0u, x1 = (unsigned int)w;
    x0 += ks[0]; x1 += ks[1];
    #pragma unroll
    for (int i = 0; i < 5; i++) {
        #pragma unroll
        for (int r = 0; r < 4; r++) {
            unsigned int rot = (i & 1) ? rotB[r] : rotA[r];
            x0 += x1; x1 = rotl32(x1, rot); x1 ^= x0;
        }
        x0 += ks[(i + 1) % 3];
        x1 += ks[(i + 2) % 3] + (unsigned int)(i + 1);
    }
    unsigned int bits = x0 ^ x1;
    float f = __uint_as_float((bits >> 9) | 0x3F800000u) - 1.0f;
    float u = fmaxf(f, 1.17549435e-38f);
    float g = -logf(-logf(u));
    float s = (w > 0) ? (logf((float)w) + g) : -INFINITY;
    unsigned int b = __float_as_uint(s);
    unsigned int m = (b & 0x80000000u) ? ~b : (b | 0x80000000u);
    g_scores[w] = m;
}

__global__ void __launch_bounds__(SEL_THREADS) k_select(float* __restrict__ out) {
    __shared__ unsigned int s[NNODES];
    __shared__ unsigned int hist[256];
    __shared__ unsigned int sh_b, sh_rem, sh_run_eq, sh_run_sel;
    typedef cub::BlockScan<unsigned int, SEL_THREADS> Scan;
    __shared__ typename Scan::TempStorage scan_tmp;

    int tid = threadIdx.x;
    for (int e = tid; e < NNODES; e += SEL_THREADS) s[e] = g_scores[e];
    if (tid == 0) { sh_rem = BATCH; sh_run_eq = 0; sh_run_sel = 0; }
    __syncthreads();

    unsigned int prefix = 0;
    #pragma unroll
    for (int shift = 24; shift >= 0; shift -= 8) {
        if (tid < 256) hist[tid] = 0;
        __syncthreads();
        unsigned int mask_hi = (shift == 24) ? 0u : (0xFFFFFFFFu << (shift + 8));
        for (int e = tid; e < NNODES; e += SEL_THREADS) {
            unsigned int v = s[e];
            if (((v ^ prefix) & mask_hi) == 0u)
                atomicAdd(&hist[(v >> shift) & 255u], 1u);
        }
        __syncthreads();
        if (tid == 0) {
            unsigned int rem = sh_rem, acc = 0; int b = 0;
            for (int k = 255; k >= 0; k--) {
                unsigned int c = hist[k];
                if (acc + c >= rem) { b = k; break; }
                acc += c;
            }
            sh_b = (unsigned int)b; sh_rem = rem - acc;
        }
        __syncthreads();
        prefix |= sh_b << shift;
        __syncthreads();
    }
    unsigned int thr = prefix, rem = sh_rem;

    for (int base = 0; base < NNODES; base += SEL_THREADS) {
        int e = base + tid;
        unsigned int v = (e < NNODES) ? s[e] : 0u;
        unsigned int is_eq = (e < NNODES && v == thr) ? 1u : 0u;
        unsigned int is_gt = (e < NNODES && v >  thr) ? 1u : 0u;
        unsigned int eq_rank, eq_tot;
        Scan(scan_tmp).ExclusiveSum(is_eq, eq_rank, eq_tot);
        __syncthreads();
        unsigned int sel = is_gt | ((is_eq && (sh_run_eq + eq_rank) < rem) ? 1u : 0u);
        unsigned int pos, sel_tot;
        Scan(scan_tmp).ExclusiveSum(sel, pos, sel_tot);
        __syncthreads();
        unsigned int gpos = sh_run_sel + pos;
        if (e < NNODES) {
            g_flags[e] = (int)sel;
            if (sel) { g_nodes[gpos] = (unsigned int)e; out[gpos] = (float)e; }
        }
        __syncthreads();
        if (tid == 0) { sh_run_eq += eq_tot; sh_run_sel += sel_tot; }
        __syncthreads();
    }
}

__global__ void k_pairs(float* __restrict__ out) {
    int p = blockIdx.x * blockDim.x + threadIdx.x;
    if (p >= NPAIRS) return;
    const float A = 2.0f * BATCH - 1.0f;
    float disc = A * A - 8.0f * (float)p;
    int i = (int)((A - sqrtf(fmaxf(disc, 0.0f))) * 0.5f);
    if (i < 0) i = 0;
    if (i > BATCH - 2) i = BATCH - 2;
    while (i > 0 && (long long)i * (2 * BATCH - i - 1) / 2 > (long long)p) i--;
    while ((long long)(i + 1) * (2 * BATCH - i - 2) / 2 <= (long long)p) i++;
    long long bse = (long long)i * (2 * BATCH - i - 1) / 2;
    int j = i + 1 + (int)((long long)p - bse);
    out[BATCH + p]          = (float)__ldg(&g_nodes[i]);
    out[BATCH + NPAIRS + p] = (float)__ldg(&g_nodes[j]);
}

// ---------------- keygen: key = flat<<6 | state, val = time -----------------
__global__ void k_ekeys4(const int* __restrict__ edges,
                         const float* __restrict__ times,
                         const int* __restrict__ states, int E) {
    int t4 = (blockIdx.x * blockDim.x + threadIdx.x) * 4;
    if (t4 >= E) return;
    if (t4 + 3 < E) {
        int4 iv = *(const int4*)(edges + t4);
        int4 jv = *(const int4*)(edges + E + t4);
        int4 sv = *(const int4*)(states + t4);
        uint4 tv = *(const uint4*)((const unsigned int*)times + t4);
        uint4 kv;
        kv.x = ((unsigned int)(iv.x * NNODES - (iv.x * (iv.x + 1)) / 2 + (jv.x - iv.x - 1)) << 6) | ((unsigned int)sv.x & 1u);
        kv.y = ((unsigned int)(iv.y * NNODES - (iv.y * (iv.y + 1)) / 2 + (jv.y - iv.y - 1)) << 6) | ((unsigned int)sv.y & 1u);
        kv.z = ((unsigned int)(iv.z * NNODES - (iv.z * (iv.z + 1)) / 2 + (jv.z - iv.z - 1)) << 6) | ((unsigned int)sv.z & 1u);
        kv.w = ((unsigned int)(iv.w * NNODES - (iv.w * (iv.w + 1)) / 2 + (jv.w - iv.w - 1)) << 6) | ((unsigned int)sv.w & 1u);
        *(uint4*)(g_kin + t4) = kv;
        *(uint4*)(g_vin + t4) = tv;
    } else {
        for (int t = t4; t < E; t++) {
            int i = edges[t], j = edges[E + t];
            unsigned int flat = (unsigned int)(i * NNODES - (i * (i + 1)) / 2 + (j - i - 1));
            g_kin[t] = (flat << 6) | ((unsigned int)states[t] & 1u);
            g_vin[t] = __float_as_uint(times[t]);
        }
    }
}

// ---------------- hist pass: per-block 4-bin counts (convergent ballots) ----
__global__ void __launch_bounds__(256) k_hist4(const unsigned int* __restrict__ keys,
                                               int E, int chunk) {
    __shared__ unsigned int h[4];
    int b = blockIdx.x;
    int start = b * chunk, end = min(E, start + chunk);
    if (threadIdx.x < 4) h[threadIdx.x] = 0;
    __syncthreads();
    int w = threadIdx.x >> 5, lane = threadIdx.x & 31;
    unsigned int c0 = 0, c1 = 0, c2 = 0, c3 = 0;
    // full-warp uniform tile loop: all 32 lanes take identical trip counts
    for (int t0 = start + w * 32; t0 < end; t0 += 256) {
        int t = t0 + lane;
        bool act = t < end;
        unsigned int bin = act ? (keys[t] >> 30) : 0xFFu;
        unsigned int m0 = __ballot_sync(0xFFFFFFFFu, bin == 0u);
        unsigned int m1 = __ballot_sync(0xFFFFFFFFu, bin == 1u);
        unsigned int m2 = __ballot_sync(0xFFFFFFFFu, bin == 2u);
        unsigned int m3 = __ballot_sync(0xFFFFFFFFu, bin == 3u);
        if (lane == 0) {
            c0 += __popc(m0); c1 += __popc(m1);
            c2 += __popc(m2); c3 += __popc(m3);
        }
    }
    if (lane == 0) {
        if (c0) atomicAdd(&h[0], c0);
        if (c1) atomicAdd(&h[1], c1);
        if (c2) atomicAdd(&h[2], c2);
        if (c3) atomicAdd(&h[3], c3);
    }
    __syncthreads();
    if (threadIdx.x < 4) g_hist4[b * 4 + threadIdx.x] = h[threadIdx.x];
}

// ---------------- scan: per-block bases + bin bases -------------------------
__global__ void __launch_bounds__(PB) k_scan4() {
    typedef cub::BlockScan<unsigned int, PB> Scan;
    __shared__ typename Scan::TempStorage tmp;
    __shared__ unsigned int tot[4];
    int t = threadIdx.x;
    unsigned int v[4];
    #pragma unroll
    for (int c = 0; c < 4; c++) v[c] = g_hist4[t * 4 + c];
    #pragma unroll
    for (int c = 0; c < 4; c++) {
        unsigned int pre, agg;
        Scan(tmp).ExclusiveSum(v[c], pre, agg);
        g_hist4[t * 4 + c] = pre;
        if (t == 0) tot[c] = agg;
        __syncthreads();
    }
    if (t == 0) {
        unsigned int off = 0;
        #pragma unroll
        for (int c = 0; c < 4; c++) { g_base4[c] = off; off += tot[c]; }
    }
}

// ---------------- flat -> (i,j) decode ---------------------------------------
__device__ __forceinline__ long long rowbase(int i) {
    return (long long)i * (2 * NNODES - 1 - i) / 2;
}
__device__ __forceinline__ void decode_flat(unsigned int flat, int& i, int& j) {
    const float A = 2.0f * NNODES - 1.0f;
    float disc = A * A - 8.0f * (float)flat;
    i = (int)((A - sqrtf(fmaxf(disc, 0.0f))) * 0.5f);
    if (i < 0) i = 0;
    if (i > NNODES - 2) i = NNODES - 2;
    while (i > 0 && rowbase(i) > (long long)flat) i--;
    while (rowbase(i + 1) <= (long long)flat) i++;
    j = (int)((long long)flat - rowbase(i)) + i + 1;
}

// ---------------- finish: stable 4-bin partition fused with epilogue --------
// Warp-owned contiguous sub-chunks + warp-private counters: 2 block barriers.
// All warp ops use full-mask convergent ballots over uniform tile loops.
// Stability: block order (hist prefix) > warp order (sweep-A prefix) >
// tile order > lane order (ballot rank). Fully deterministic.
__global__ void __launch_bounds__(256) k_finish(const unsigned int* __restrict__ keys,
                                                const unsigned int* __restrict__ vals,
                                                float* __restrict__ out, int E, int chunk) {
    __shared__ unsigned int wcnt[8][4];
    __shared__ unsigned int hpb[4];
    int blk = blockIdx.x;
    int start = blk * chunk, end = min(E, start + chunk);
    int n = end - start;
    if (n <= 0) return;
    int tid = threadIdx.x, w = tid >> 5, lane = tid & 31;

    // warp sub-chunks (contiguous, in order)
    int per = (n + 7) / 8;
    int s0 = start + w * per;
    int s1 = min(end, s0 + per);

    // sweep A: per-warp per-bin counts via convergent full-warp ballots
    {
        unsigned int c0 = 0, c1 = 0, c2 = 0, c3 = 0;
        for (int t0 = s0; t0 < s1; t0 += 32) {
            int t = t0 + lane;
            bool act = t < s1;
            unsigned int bin = act ? (keys[t] >> 30) : 0xFFu;
            unsigned int m0 = __ballot_sync(0xFFFFFFFFu, bin == 0u);
            unsigned int m1 = __ballot_sync(0xFFFFFFFFu, bin == 1u);
            unsigned int m2 = __ballot_sync(0xFFFFFFFFu, bin == 2u);
            unsigned int m3 = __ballot_sync(0xFFFFFFFFu, bin == 3u);
            if (lane == 0) {
                c0 += __popc(m0); c1 += __popc(m1);
                c2 += __popc(m2); c3 += __popc(m3);
            }
        }
        if (lane == 0) {
            wcnt[w][0] = c0; wcnt[w][1] = c1; wcnt[w][2] = c2; wcnt[w][3] = c3;
        }
    }
    __syncthreads();

    // per-bin exclusive prefix over warps + global bases (threads 0..3)
    if (tid < 4) {
        unsigned int acc = 0;
        #pragma unroll
        for (int ww = 0; ww < 8; ww++) {
            unsigned int c = wcnt[ww][tid];
            wcnt[ww][tid] = acc;
            acc += c;
        }
        hpb[tid] = g_base4[tid] + g_hist4[blk * 4 + tid];
    }
    __syncthreads();

    const long long OFF_E = (long long)BATCH + 2LL * NPAIRS;
    const long long OFF_T = OFF_E + 2LL * E;
    const long long OFF_S = OFF_T + E;
    const long long OFF_M = OFF_S + E;

    // sweep B: ordered deterministic scatter + epilogue (full-warp tiles)
    for (int t0 = s0; t0 < s1; t0 += 32) {
        int t = t0 + lane;
        bool act = t < s1;
        unsigned int key = act ? keys[t] : 0u;
        int bin = act ? (int)(key >> 30) : -1;
        unsigned int rank = 0;
        unsigned int base = 0;
        #pragma unroll
        for (int bb = 0; bb < 4; bb++) {
            unsigned int m = __ballot_sync(0xFFFFFFFFu, bin == bb);
            if (m) {
                if (bin == bb) rank = __popc(m & ((1u << lane) - 1u));
                int leader = __ffs(m) - 1;
                unsigned int bs = 0;
                if (lane == leader) bs = atomicAdd(&wcnt[w][bb], __popc(m));
                bs = __shfl_sync(0xFFFFFFFFu, bs, leader);
                if (bin == bb) base = bs;
            }
        }
        if (act) {
            unsigned int pos = hpb[bin] + base + rank;
            unsigned int flat = key >> 6;
            int st = (int)(key & 1u);
            int i, j; decode_flat(flat, i, j);
            int m = g_flags[i] & g_flags[j];
            float tm = __uint_as_float(vals[t]);
            out[OFF_E + pos]     = (float)i;
            out[OFF_E + E + pos] = (float)j;
            out[OFF_T + pos]     = m ? tm : 0.0f;
            out[OFF_S + pos]     = m ? (float)st : 0.0f;
            out[OFF_M + pos]     = (float)m;
        }
    }
}

// ---------------- launcher ---------------------------------------------------
extern "C" void kernel_launch(void* const* d_in, const int* in_sizes, int n_in,
                              void* d_out, int out_size) {
    const int*   edges  = (const int*)d_in[0];
    const float* times  = (const float*)d_in[1];
    const int*   states = (const int*)d_in[2];
    int E = in_sizes[1];
    if (E > EMAX) E = EMAX;
    float* out = (float*)d_out;

    static cudaStream_t s_side = nullptr;
    static cudaEvent_t ev_fork = nullptr, ev_join = nullptr;
    if (s_side == nullptr) {
        cudaStreamCreateWithFlags(&s_side, cudaStreamNonBlocking);
        cudaEventCreateWithFlags(&ev_fork, cudaEventDisableTiming);
        cudaEventCreateWithFlags(&ev_join, cudaEventDisableTiming);
    }

    void *kin, *kout, *vin, *vout, *temp;
    cudaGetSymbolAddress(&kin,  g_kin);
    cudaGetSymbolAddress(&kout, g_kout);
    cudaGetSymbolAddress(&vin,  g_vin);
    cudaGetSymbolAddress(&vout, g_vout);
    cudaGetSymbolAddress(&temp, g_temp);
    const size_t temp_cap = 96u * 1024u * 1024u;

    // ---- fork: node chain on the single proven side stream ------------------
    cudaEventRecord(ev_fork, 0);
    cudaStreamWaitEvent(s_side, ev_fork, 0);
    k_scores<<<(NNODES + 255) / 256, 256, 0, s_side>>>();
    k_select<<<1, SEL_THREADS, 0, s_side>>>(out);
    k_pairs<<<(NPAIRS + 255) / 256, 256, 0, s_side>>>(out);
    cudaEventRecord(ev_join, s_side);

    // ---- main: keygen -------------------------------------------------------
    k_ekeys4<<<(E / 4 + 255) / 256, 256>>>(edges, times, states, E);

    // ---- 3-pass stable radix sort on bits [6,30) ----------------------------
    cub::DoubleBuffer<unsigned int> dk((unsigned int*)kin, (unsigned int*)kout);
    cub::DoubleBuffer<unsigned int> dv((unsigned int*)vin, (unsigned int*)vout);
    size_t tb = 0;
    cub::DeviceRadixSort::SortPairs(nullptr, tb, dk, dv, E, 6, 30);
    if (tb > temp_cap) tb = temp_cap;
    cub::DeviceRadixSort::SortPairs(temp, tb, dk, dv, E, 6, 30);
    const unsigned int* skeys = dk.Current();
    const unsigned int* svals = dv.Current();

    // ---- stable 4-bin partition on bits [30,32) fused with epilogue ---------
    int chunk = (E + PB - 1) / PB;
    k_hist4<<<PB, 256>>>(skeys, E, chunk);
    k_scan4<<<1, PB>>>();
    cudaStreamWaitEvent(0, ev_join, 0);
    k_finish<<<PB, 256>>>(skeys, svals, out, E, chunk);
}

// round 15
// speedup vs baseline: 2.1748x; 1.1086x over previous
#include <cuda_runtime.h>
#include <cuda_bf16.h>
#include <cub/cub.cuh>
#include <math.h>

#define NNODES 10000
#define BATCH  2000
#define NPAIRS (BATCH*(BATCH-1)/2)   /* 1999000 */
#define EMAX   5000000
#define SEL_THREADS 1024
#define PB 1024                      /* finish partition blocks */

// ---------------- static device scratch (no allocations allowed) -----------
__device__ unsigned int g_kin [EMAX];
__device__ unsigned int g_kout[EMAX];
__device__ unsigned int g_vin [EMAX];
__device__ unsigned int g_vout[EMAX];
__device__ unsigned int g_look[4 * PB];     // lookback: 2-bit flag | 30-bit count
__device__ unsigned int g_cnt4[4];          // global bin totals (from keygen)
__device__ unsigned int g_base4[4];         // exclusive bin bases
__device__ unsigned int g_scores[NNODES];
__device__ unsigned int g_nodes[BATCH];
__device__ int          g_flags[NNODES];
__device__ unsigned char g_temp[96u * 1024u * 1024u];

__device__ __forceinline__ unsigned int rotl32(unsigned int x, unsigned int d) {
    return (x << d) | (x >> (32u - d));
}

// ---------------- node chain: scores / select / pairs ----------------------
__global__ void k_scores() {
    int w = blockIdx.x * blockDim.x + threadIdx.x;
    if (w >= NNODES) return;
    const unsigned int k0 = 0u, k1 = 19u;
    const unsigned int ks[3] = { k0, k1, k0 ^ k1 ^ 0x1BD11BDAu };
    const unsigned int rotA[4] = {13u, 15u, 26u, 6u};
    const unsigned int rotB[4] = {17u, 29u, 16u, 24u};
    unsigned int x0 = 0u, x1 = (unsigned int)w;
    x0 += ks[0]; x1 += ks[1];
    #pragma unroll
    for (int i = 0; i < 5; i++) {
        #pragma unroll
        for (int r = 0; r < 4; r++) {
            unsigned int rot = (i & 1) ? rotB[r] : rotA[r];
            x0 += x1; x1 = rotl32(x1, rot); x1 ^= x0;
        }
        x0 += ks[(i + 1) % 3];
        x1 += ks[(i + 2) % 3] + (unsigned int)(i + 1);
    }
    unsigned int bits = x0 ^ x1;
    float f = __uint_as_float((bits >> 9) | 0x3F800000u) - 1.0f;
    float u = fmaxf(f, 1.17549435e-38f);
    float g = -logf(-logf(u));
    float s = (w > 0) ? (logf((float)w) + g) : -INFINITY;
    unsigned int b = __float_as_uint(s);
    unsigned int m = (b & 0x80000000u) ? ~b : (b | 0x80000000u);
    g_scores[w] = m;
}

__global__ void __launch_bounds__(SEL_THREADS) k_select(float* __restrict__ out) {
    __shared__ unsigned int s[NNODES];
    __shared__ unsigned int hist[256];
    __shared__ unsigned int sh_b, sh_rem, sh_run_eq, sh_run_sel;
    typedef cub::BlockScan<unsigned int, SEL_THREADS> Scan;
    __shared__ typename Scan::TempStorage scan_tmp;

    int tid = threadIdx.x;
    for (int e = tid; e < NNODES; e += SEL_THREADS) s[e] = g_scores[e];
    if (tid == 0) { sh_rem = BATCH; sh_run_eq = 0; sh_run_sel = 0; }
    __syncthreads();

    unsigned int prefix = 0;
    #pragma unroll
    for (int shift = 24; shift >= 0; shift -= 8) {
        if (tid < 256) hist[tid] = 0;
        __syncthreads();
        unsigned int mask_hi = (shift == 24) ? 0u : (0xFFFFFFFFu << (shift + 8));
        for (int e = tid; e < NNODES; e += SEL_THREADS) {
            unsigned int v = s[e];
            if (((v ^ prefix) & mask_hi) == 0u)
                atomicAdd(&hist[(v >> shift) & 255u], 1u);
        }
        __syncthreads();
        if (tid == 0) {
            unsigned int rem = sh_rem, acc = 0; int b = 0;
            for (int k = 255; k >= 0; k--) {
                unsigned int c = hist[k];
                if (acc + c >= rem) { b = k; break; }
                acc += c;
            }
            sh_b = (unsigned int)b; sh_rem = rem - acc;
        }
        __syncthreads();
        prefix |= sh_b << shift;
        __syncthreads();
    }
    unsigned int thr = prefix, rem = sh_rem;

    for (int base = 0; base < NNODES; base += SEL_THREADS) {
        int e = base + tid;
        unsigned int v = (e < NNODES) ? s[e] : 0u;
        unsigned int is_eq = (e < NNODES && v == thr) ? 1u : 0u;
        unsigned int is_gt = (e < NNODES && v >  thr) ? 1u : 0u;
        unsigned int eq_rank, eq_tot;
        Scan(scan_tmp).ExclusiveSum(is_eq, eq_rank, eq_tot);
        __syncthreads();
        unsigned int sel = is_gt | ((is_eq && (sh_run_eq + eq_rank) < rem) ? 1u : 0u);
        unsigned int pos, sel_tot;
        Scan(scan_tmp).ExclusiveSum(sel, pos, sel_tot);
        __syncthreads();
        unsigned int gpos = sh_run_sel + pos;
        if (e < NNODES) {
            g_flags[e] = (int)sel;
            if (sel) { g_nodes[gpos] = (unsigned int)e; out[gpos] = (float)e; }
        }
        __syncthreads();
        if (tid == 0) { sh_run_eq += eq_tot; sh_run_sel += sel_tot; }
        __syncthreads();
    }
}

__global__ void k_pairs(float* __restrict__ out) {
    int p = blockIdx.x * blockDim.x + threadIdx.x;
    if (p >= NPAIRS) return;
    const float A = 2.0f * BATCH - 1.0f;
    float disc = A * A - 8.0f * (float)p;
    int i = (int)((A - sqrtf(fmaxf(disc, 0.0f))) * 0.5f);
    if (i < 0) i = 0;
    if (i > BATCH - 2) i = BATCH - 2;
    while (i > 0 && (long long)i * (2 * BATCH - i - 1) / 2 > (long long)p) i--;
    while ((long long)(i + 1) * (2 * BATCH - i - 2) / 2 <= (long long)p) i++;
    long long bse = (long long)i * (2 * BATCH - i - 1) / 2;
    int j = i + 1 + (int)((long long)p - bse);
    out[BATCH + p]          = (float)__ldg(&g_nodes[i]);
    out[BATCH + NPAIRS + p] = (float)__ldg(&g_nodes[j]);
}

// ---------------- zero lookback state + bin totals ---------------------------
__global__ void k_zero_look() {
    int t = blockIdx.x * blockDim.x + threadIdx.x;
    if (t < 4 * PB) g_look[t] = 0u;
    if (t < 4) g_cnt4[t] = 0u;
}

// ---------------- keygen: key = flat<<6 | state, val = time; bin totals -----
__global__ void __launch_bounds__(256) k_ekeys4(const int* __restrict__ edges,
                                                const float* __restrict__ times,
                                                const int* __restrict__ states, int E) {
    __shared__ unsigned int h[4];
    if (threadIdx.x < 4) h[threadIdx.x] = 0;
    __syncthreads();

    int t4 = (blockIdx.x * blockDim.x + threadIdx.x) * 4;
    if (t4 < E) {
        if (t4 + 3 < E) {
            int4 iv = *(const int4*)(edges + t4);
            int4 jv = *(const int4*)(edges + E + t4);
            int4 sv = *(const int4*)(states + t4);
            uint4 tv = *(const uint4*)((const unsigned int*)times + t4);
            uint4 kv;
            kv.x = ((unsigned int)(iv.x * NNODES - (iv.x * (iv.x + 1)) / 2 + (jv.x - iv.x - 1)) << 6) | ((unsigned int)sv.x & 1u);
            kv.y = ((unsigned int)(iv.y * NNODES - (iv.y * (iv.y + 1)) / 2 + (jv.y - iv.y - 1)) << 6) | ((unsigned int)sv.y & 1u);
            kv.z = ((unsigned int)(iv.z * NNODES - (iv.z * (iv.z + 1)) / 2 + (jv.z - iv.z - 1)) << 6) | ((unsigned int)sv.z & 1u);
            kv.w = ((unsigned int)(iv.w * NNODES - (iv.w * (iv.w + 1)) / 2 + (jv.w - iv.w - 1)) << 6) | ((unsigned int)sv.w & 1u);
            *(uint4*)(g_kin + t4) = kv;
            *(uint4*)(g_vin + t4) = tv;
            atomicAdd(&h[kv.x >> 30], 1u);
            atomicAdd(&h[kv.y >> 30], 1u);
            atomicAdd(&h[kv.z >> 30], 1u);
            atomicAdd(&h[kv.w >> 30], 1u);
        } else {
            for (int t = t4; t < E; t++) {
                int i = edges[t], j = edges[E + t];
                unsigned int flat = (unsigned int)(i * NNODES - (i * (i + 1)) / 2 + (j - i - 1));
                unsigned int key = (flat << 6) | ((unsigned int)states[t] & 1u);
                g_kin[t] = key;
                g_vin[t] = __float_as_uint(times[t]);
                atomicAdd(&h[key >> 30], 1u);
            }
        }
    }
    __syncthreads();
    if (threadIdx.x < 4 && h[threadIdx.x]) atomicAdd(&g_cnt4[threadIdx.x], h[threadIdx.x]);
}

// ---------------- bin bases: tiny exclusive prefix of 4 ----------------------
__global__ void k_base4() {
    if (threadIdx.x == 0) {
        unsigned int off = 0;
        #pragma unroll
        for (int c = 0; c < 4; c++) { g_base4[c] = off; off += g_cnt4[c]; }
    }
}

// ---------------- flat -> (i,j) decode ---------------------------------------
__device__ __forceinline__ long long rowbase(int i) {
    return (long long)i * (2 * NNODES - 1 - i) / 2;
}
__device__ __forceinline__ void decode_flat(unsigned int flat, int& i, int& j) {
    const float A = 2.0f * NNODES - 1.0f;
    float disc = A * A - 8.0f * (float)flat;
    i = (int)((A - sqrtf(fmaxf(disc, 0.0f))) * 0.5f);
    if (i < 0) i = 0;
    if (i > NNODES - 2) i = NNODES - 2;
    while (i > 0 && rowbase(i) > (long long)flat) i--;
    while (rowbase(i + 1) <= (long long)flat) i++;
    j = (int)((long long)flat - rowbase(i)) + i + 1;
}

// ---------------- finish: lookback 4-bin partition fused with epilogue ------
// Sweep A: block's 4-bin counts (R7 hist code). Decoupled lookback gives the
// exclusive per-bin base; sweep B is R7's proven ordered scatter + epilogue.
__global__ void __launch_bounds__(256) k_finish(const unsigned int* __restrict__ keys,
                                                const unsigned int* __restrict__ vals,
                                                float* __restrict__ out, int E, int chunk) {
    __shared__ unsigned int h[4];
    __shared__ unsigned int run[4];
    __shared__ unsigned int wcnt[8][4];
    __shared__ unsigned int ttot[4];
    int blk = blockIdx.x;
    int start = blk * chunk, end = min(E, start + chunk);

    if (threadIdx.x < 4) h[threadIdx.x] = 0;
    __syncthreads();

    if (end <= start) {
        // empty chunk: publish zero aggregate so successors don't spin
        if (threadIdx.x < 4)
            atomicExch(&g_look[threadIdx.x * PB + blk], (1u << 30));
        return;
    }

    // sweep A: per-block 4-bin counts
    for (int t = start + threadIdx.x; t < end; t += blockDim.x)
        atomicAdd(&h[keys[t] >> 30], 1u);
    __syncthreads();

    // publish aggregate, lookback for exclusive base, publish inclusive
    if (threadIdx.x < 4) {
        int c = threadIdx.x;
        unsigned int agg = h[c];
        if (blk == 0) {
            atomicExch(&g_look[c * PB], (2u << 30) | agg);
            run[c] = g_base4[c];
        } else {
            atomicExch(&g_look[c * PB + blk], (1u << 30) | agg);
            unsigned int excl = 0;
            int p = blk - 1;
            while (p >= 0) {
                unsigned int v = atomicAdd(&g_look[c * PB + p], 0u);
                unsigned int fl = v >> 30;
                if (fl == 0u) continue;              // not ready yet: spin
                excl += v & 0x3FFFFFFFu;
                if (fl == 2u) break;                 // inclusive found
                p--;
            }
            atomicExch(&g_look[c * PB + blk], (2u << 30) | (excl + agg));
            run[c] = g_base4[c] + excl;
        }
    }
    __syncthreads();

    const long long OFF_E = (long long)BATCH + 2LL * NPAIRS;
    const long long OFF_T = OFF_E + 2LL * E;
    const long long OFF_S = OFF_T + E;
    const long long OFF_M = OFF_S + E;

    // sweep B: R7's proven ordered deterministic scatter + epilogue
    int warp = threadIdx.x >> 5, lane = threadIdx.x & 31;
    for (int base = start; base < end; base += blockDim.x) {
        int t = base + threadIdx.x;
        unsigned int key = 0, val = 0;
        int c = -1;
        if (t < end) { key = keys[t]; val = vals[t]; c = (int)(key >> 30); }
        unsigned int rank = 0;
        #pragma unroll
        for (int cc = 0; cc < 4; cc++) {
            unsigned int m = __ballot_sync(0xFFFFFFFFu, c == cc);
            if (c == cc) rank = __popc(m & ((1u << lane) - 1u));
            if (lane == 0) wcnt[warp][cc] = __popc(m);
        }
        __syncthreads();
        if (threadIdx.x < 4) {
            unsigned int acc = 0;
            #pragma unroll
            for (int w = 0; w < 8; w++) {
                unsigned int v = wcnt[w][threadIdx.x];
                wcnt[w][threadIdx.x] = acc;
                acc += v;
            }
            ttot[threadIdx.x] = acc;
        }
        __syncthreads();
        if (t < end) {
            unsigned int pos = run[c] + wcnt[warp][c] + rank;  // final sorted slot
            unsigned int flat = key >> 6;
            int st = (int)(key & 1u);
            int i, j; decode_flat(flat, i, j);
            int m = g_flags[i] & g_flags[j];
            out[OFF_E + pos]     = (float)i;
            out[OFF_E + E + pos] = (float)j;
            out[OFF_T + pos]     = m ? __uint_as_float(val) : 0.0f;
            out[OFF_S + pos]     = m ? (float)st : 0.0f;
            out[OFF_M + pos]     = (float)m;
        }
        __syncthreads();
        if (threadIdx.x < 4) run[threadIdx.x] += ttot[threadIdx.x];
        __syncthreads();
    }
}

// ---------------- launcher ---------------------------------------------------
extern "C" void kernel_launch(void* const* d_in, const int* in_sizes, int n_in,
                              void* d_out, int out_size) {
    const int*   edges  = (const int*)d_in[0];
    const float* times  = (const float*)d_in[1];
    const int*   states = (const int*)d_in[2];
    int E = in_sizes[1];
    if (E > EMAX) E = EMAX;
    float* out = (float*)d_out;

    static cudaStream_t s_side = nullptr;
    static cudaEvent_t ev_fork = nullptr, ev_join = nullptr;
    if (s_side == nullptr) {
        cudaStreamCreateWithFlags(&s_side, cudaStreamNonBlocking);
        cudaEventCreateWithFlags(&ev_fork, cudaEventDisableTiming);
        cudaEventCreateWithFlags(&ev_join, cudaEventDisableTiming);
    }

    void *kin, *kout, *vin, *vout, *temp;
    cudaGetSymbolAddress(&kin,  g_kin);
    cudaGetSymbolAddress(&kout, g_kout);
    cudaGetSymbolAddress(&vin,  g_vin);
    cudaGetSymbolAddress(&vout, g_vout);
    cudaGetSymbolAddress(&temp, g_temp);
    const size_t temp_cap = 96u * 1024u * 1024u;

    // ---- fork: node chain on the single proven side stream ------------------
    cudaEventRecord(ev_fork, 0);
    cudaStreamWaitEvent(s_side, ev_fork, 0);
    k_scores<<<(NNODES + 255) / 256, 256, 0, s_side>>>();
    k_select<<<1, SEL_THREADS, 0, s_side>>>(out);
    k_pairs<<<(NPAIRS + 255) / 256, 256, 0, s_side>>>(out);
    cudaEventRecord(ev_join, s_side);

    // ---- main: reset lookback state, keygen (+bin totals), bin bases --------
    k_zero_look<<<(4 * PB + 255) / 256, 256>>>();
    k_ekeys4<<<(E / 4 + 255) / 256, 256>>>(edges, times, states, E);
    k_base4<<<1, 32>>>();

    // ---- 3-pass stable radix sort on bits [6,30) ----------------------------
    cub::DoubleBuffer<unsigned int> dk((unsigned int*)kin, (unsigned int*)kout);
    cub::DoubleBuffer<unsigned int> dv((unsigned int*)vin, (unsigned int*)vout);
    size_t tb = 0;
    cub::DeviceRadixSort::SortPairs(nullptr, tb, dk, dv, E, 6, 30);
    if (tb > temp_cap) tb = temp_cap;
    cub::DeviceRadixSort::SortPairs(temp, tb, dk, dv, E, 6, 30);
    const unsigned int* skeys = dk.Current();
    const unsigned int* svals = dv.Current();

    // ---- join node chain (flags), then lookback partition + epilogue --------
    int chunk = (E + PB - 1) / PB;
    cudaStreamWaitEvent(0, ev_join, 0);
    k_finish<<<PB, 256>>>(skeys, svals, out, E, chunk);
}